// round 6
// baseline (speedup 1.0000x reference)
#include <cuda_runtime.h>
#include <cuda_bf16.h>
#include <math.h>
#include <stdint.h>

// Problem constants
#define BB   4
#define LSEQ 4096
#define HD   1024
#define UD   1024
#define U3   3072
#define NCHUNK 64
#define LC     64
#define K2   2048           // stored split K: [hi | lo]
#define MROWS (BB*LSEQ)     // 16384

// Scratch (allocation-free: __device__ globals)
__device__ float g_rkv[(size_t)BB * LSEQ * U3];        // 192 MB fp32
__device__ float g_x[(size_t)BB * LSEQ * UD];          // 64 MB
__device__ float g_part[(size_t)BB * NCHUNK * 2 * UD]; // 2 MB
__device__ __nv_bfloat16 g_Ah[(size_t)MROWS * K2];     // 64 MB: split(inputs)
__device__ __nv_bfloat16 g_Xh[(size_t)MROWS * K2];     // 64 MB: split(x)
__device__ __nv_bfloat16 g_B1[(size_t)U3 * K2];        // 12 MB: split+T(W_rkv)
__device__ __nv_bfloat16 g_B2[(size_t)HD * K2];        //  4 MB: split+T(W_o)

__device__ __forceinline__ void cpa16(void* s, const void* g) {
    uint32_t sa = (uint32_t)__cvta_generic_to_shared(s);
    asm volatile("cp.async.cg.shared.global [%0], [%1], 16;" :: "r"(sa), "l"(g));
}

// ---------------------------------------------------------------------------
// bf16 warp-MMA GEMM (mma.sync m16n8k16, fp32 accum), 3-term hi/lo split:
//   C = A_hi*B_hi + A_hi*B_lo + A_lo*B_hi   (~fp32 accuracy)
// 96 virtual K-chunks of 32. CTA tile 128x256, 8 warps (2x4), warp tile 64x64.
// 3-stage cp.async pipeline (1 barrier/chunk), ldmatrix.x4 fragment loads
// for BOTH A and B -> MMA:LDSM = 4:1.
// SMEM rows padded to 40 bf16 (80B): 16B-aligned, conflict-free ldmatrix.
// ---------------------------------------------------------------------------
#define RS    40                // row stride (bf16 elems)
#define ATEL  (128 * RS)        // A tile elems
#define BTEL  (256 * RS)        // B tile elems
#define SEL   (ATEL + BTEL)     // elems per stage
#define STB   (SEL * 2)         // bytes per stage (30720)
#define SMEM_GEMM (3 * STB)     // 92160 bytes

__global__ void __launch_bounds__(256, 1) gemm_mma(
    const __nv_bfloat16* __restrict__ A,
    const __nv_bfloat16* __restrict__ Bt,
    const float* __restrict__ bias,
    float* __restrict__ C, int N)
{
    extern __shared__ __nv_bfloat16 smbuf[];
    const uint32_t smem0 = (uint32_t)__cvta_generic_to_shared(smbuf);

    const int tid  = threadIdx.x;
    const int m0   = blockIdx.y * 128;
    const int n0   = blockIdx.x * 256;
    const int warp = tid >> 5;
    const int lane = tid & 31;
    const int wm   = (warp >> 2) * 64;   // 0 or 64
    const int wn   = (warp & 3) * 64;    // 0,64,128,192
    const int gm   = lane >> 2;          // 0..7
    const int kq   = (lane & 3) * 2;     // 0,2,4,6

    // ldmatrix.x4 per-lane base offsets (bytes, within a stage)
    // A (m16 x k16): matrices ordered m-half, m-half+8, then k-half
    const uint32_t aOff = (uint32_t)(((wm + (lane & 7) + ((lane >> 3) & 1) * 8) * RS
                                      + (lane >> 4) * 8) * 2);
    // B (two n8 blocks x k16): matrices ordered k-half first, then n-half
    const uint32_t bOff = (uint32_t)(ATEL * 2 +
                                     ((wn + (lane & 7) + ((lane >> 4) & 1) * 8) * RS
                                      + ((lane >> 3) & 1) * 8) * 2);

    float acc[4][8][4];
    #pragma unroll
    for (int i = 0; i < 4; i++)
        #pragma unroll
        for (int j = 0; j < 8; j++)
            #pragma unroll
            for (int t = 0; t < 4; t++)
                acc[i][j][t] = 0.f;

    // loader: virtual chunk ci (0..95) -> stage st
    const int lr = tid >> 2;        // 0..63 base row
    const int lj = (tid & 3) * 8;   // 16B segment within 64B row-chunk
    auto load_chunk = [&](int ci, int st) {
        const int s   = ci >> 5;            // segment 0,1,2
        const int kof = (ci & 31) << 5;     // 0..992
        const size_t kA = (size_t)((s == 2) ? 1024 : 0) + kof;   // A: hi,hi,lo
        const size_t kB = (size_t)((s == 1) ? 1024 : 0) + kof;   // B: hi,lo,hi
        __nv_bfloat16* As = smbuf + (size_t)st * SEL;
        __nv_bfloat16* Bs = As + ATEL;
        #pragma unroll
        for (int h = 0; h < 2; h++) {       // A: 128 rows
            int r = lr + h * 64;
            cpa16(As + r * RS + lj, A + (size_t)(m0 + r) * K2 + kA + lj);
        }
        #pragma unroll
        for (int h = 0; h < 4; h++) {       // B: 256 rows
            int r = lr + h * 64;
            cpa16(Bs + r * RS + lj, Bt + (size_t)(n0 + r) * K2 + kB + lj);
        }
        asm volatile("cp.async.commit_group;");
    };

    load_chunk(0, 0);
    load_chunk(1, 1);

    const int NCH = 96;
    for (int ci = 0; ci < NCH; ci++) {
        const int st = ci % 3;
        if (ci < NCH - 1) {
            asm volatile("cp.async.wait_group 1;" ::: "memory");
        } else {
            asm volatile("cp.async.wait_group 0;" ::: "memory");
        }
        __syncthreads();
        if (ci + 2 < NCH) load_chunk(ci + 2, (ci + 2) % 3);

        const uint32_t aBase = smem0 + (uint32_t)st * STB + aOff;
        const uint32_t bBase = smem0 + (uint32_t)st * STB + bOff;

        #pragma unroll
        for (int kk = 0; kk < 2; kk++) {
            uint32_t af[4][4], bf[8][2];
            #pragma unroll
            for (int i = 0; i < 4; i++)
                asm volatile(
                    "ldmatrix.sync.aligned.m8n8.x4.shared.b16 {%0,%1,%2,%3}, [%4];"
                    : "=r"(af[i][0]), "=r"(af[i][1]), "=r"(af[i][2]), "=r"(af[i][3])
                    : "r"(aBase + (uint32_t)(i * 16 * RS * 2 + kk * 32)));
            #pragma unroll
            for (int j = 0; j < 4; j++)
                asm volatile(
                    "ldmatrix.sync.aligned.m8n8.x4.shared.b16 {%0,%1,%2,%3}, [%4];"
                    : "=r"(bf[2*j][0]), "=r"(bf[2*j][1]),
                      "=r"(bf[2*j+1][0]), "=r"(bf[2*j+1][1])
                    : "r"(bBase + (uint32_t)(j * 16 * RS * 2 + kk * 32)));
            #pragma unroll
            for (int i = 0; i < 4; i++)
                #pragma unroll
                for (int j = 0; j < 8; j++)
                    asm volatile(
                        "mma.sync.aligned.m16n8k16.row.col.f32.bf16.bf16.f32 "
                        "{%0,%1,%2,%3}, {%4,%5,%6,%7}, {%8,%9}, {%0,%1,%2,%3};"
                        : "+f"(acc[i][j][0]), "+f"(acc[i][j][1]),
                          "+f"(acc[i][j][2]), "+f"(acc[i][j][3])
                        : "r"(af[i][0]), "r"(af[i][1]), "r"(af[i][2]), "r"(af[i][3]),
                          "r"(bf[j][0]), "r"(bf[j][1]));
        }
    }

    // Epilogue: bias + store (float2 per fragment row)
    #pragma unroll
    for (int j = 0; j < 8; j++) {
        const int col = n0 + wn + j * 8 + kq;
        const float b0 = bias[col], b1 = bias[col + 1];
        #pragma unroll
        for (int i = 0; i < 4; i++) {
            const int row = m0 + wm + i * 16 + gm;
            float2 v0 = make_float2(acc[i][j][0] + b0, acc[i][j][1] + b1);
            float2 v1 = make_float2(acc[i][j][2] + b0, acc[i][j][3] + b1);
            *(float2*)&C[(size_t)row * N + col]       = v0;
            *(float2*)&C[(size_t)(row + 8) * N + col] = v1;
        }
    }
}

// ---------------------------------------------------------------------------
// fp32 -> bf16 hi/lo split, row layout [R,1024] -> [R,2048] ([hi|lo])
// ---------------------------------------------------------------------------
__global__ void __launch_bounds__(256) split_rows(const float* __restrict__ X,
                                                  __nv_bfloat16* __restrict__ Y, int total4)
{
    int idx = blockIdx.x * 256 + threadIdx.x;
    if (idx >= total4) return;
    int r = idx >> 8;          // 256 float4 per row (K=1024)
    int c4 = idx & 255;
    float4 v = ((const float4*)X)[idx];
    float f[4] = { v.x, v.y, v.z, v.w };
    ushort4 hv, lv;
    unsigned short* hp = &hv.x; unsigned short* lp = &lv.x;
    #pragma unroll
    for (int i = 0; i < 4; i++) {
        __nv_bfloat16 h = __float2bfloat16(f[i]);
        __nv_bfloat16 l = __float2bfloat16(f[i] - __bfloat162float(h));
        hp[i] = __bfloat16_as_ushort(h);
        lp[i] = __bfloat16_as_ushort(l);
    }
    size_t o = (size_t)r * K2 + (c4 << 2);
    *(ushort4*)((unsigned short*)Y + o)         = hv;
    *(ushort4*)((unsigned short*)Y + o + 1024)  = lv;
}

// ---------------------------------------------------------------------------
// W[K,N] fp32 -> Bt[N,2048] bf16 (transpose + split), tiled 32x32
// ---------------------------------------------------------------------------
__global__ void split_T(const float* __restrict__ W, __nv_bfloat16* __restrict__ Bt,
                        int Kdim, int Ncols)
{
    __shared__ float t[32][33];
    int n = blockIdx.x * 32 + threadIdx.x;
    int k0 = blockIdx.y * 32;
    for (int i = threadIdx.y; i < 32; i += 8)
        t[i][threadIdx.x] = W[(size_t)(k0 + i) * Ncols + n];
    __syncthreads();
    int k = k0 + threadIdx.x;
    for (int i = threadIdx.y; i < 32; i += 8) {
        int nn = blockIdx.x * 32 + i;
        float v = t[threadIdx.x][i];
        __nv_bfloat16 h = __float2bfloat16(v);
        __nv_bfloat16 l = __float2bfloat16(v - __bfloat162float(h));
        Bt[(size_t)nn * K2 + k]        = h;
        Bt[(size_t)nn * K2 + 1024 + k] = l;
    }
}

// ---------------------------------------------------------------------------
// Chunked linear-recurrence scan (3 phases)
// ---------------------------------------------------------------------------
__global__ void __launch_bounds__(256) scan_phaseA(const float* __restrict__ nu_log)
{
    const int c = blockIdx.x * blockDim.x + threadIdx.x;
    const int chunk = blockIdx.y;
    const int b = blockIdx.z;
    const float lam = expf(-expf(nu_log[c]));

    size_t base = ((size_t)b * LSEQ + (size_t)chunk * LC) * U3;
    float y1 = 0.f, y2 = 0.f;
    #pragma unroll 4
    for (int i = 0; i < LC; i++) {
        size_t off = base + (size_t)i * U3;
        float kr = g_rkv[off + UD + c];
        float vr = g_rkv[off + 2 * UD + c];
        float kk = expf(kr);
        float kv = kk * vr;
        g_rkv[off + UD + c]     = kk;
        g_rkv[off + 2 * UD + c] = kv;
        y1 = fmaf(y1, lam, kv);
        y2 = fmaf(y2, lam, kk);
    }
    size_t p = (size_t)(b * NCHUNK + chunk) * 2 * UD + c;
    g_part[p]      = y1;
    g_part[p + UD] = y2;
}

__global__ void __launch_bounds__(256) scan_phaseB(const float* __restrict__ nu_log)
{
    const int c = blockIdx.x * blockDim.x + threadIdx.x;
    const int b = blockIdx.y;
    const float lam = expf(-expf(nu_log[c]));
    const float lamLc = powf(lam, (float)LC);
    float Y1 = 0.f, Y2 = 0.f;
    for (int j = 0; j < NCHUNK; j++) {
        size_t p = (size_t)(b * NCHUNK + j) * 2 * UD + c;
        float S1 = g_part[p], S2 = g_part[p + UD];
        g_part[p]      = Y1;
        g_part[p + UD] = Y2;
        Y1 = fmaf(Y1, lamLc, S1);
        Y2 = fmaf(Y2, lamLc, S2);
    }
}

__global__ void __launch_bounds__(256) scan_phaseC(const float* __restrict__ nu_log,
                                                   const float* __restrict__ gamma_log)
{
    const int c = blockIdx.x * blockDim.x + threadIdx.x;
    const int chunk = blockIdx.y;
    const int b = blockIdx.z;
    const float lam = expf(-expf(nu_log[c]));
    const float gamma = expf(nu_log[c] + gamma_log[c]) - 1.f;

    size_t p = (size_t)(b * NCHUNK + chunk) * 2 * UD + c;
    float y1 = g_part[p];
    float y2 = g_part[p + UD];

    size_t base  = ((size_t)b * LSEQ + (size_t)chunk * LC) * U3;
    size_t xbase = ((size_t)b * LSEQ + (size_t)chunk * LC) * UD;
    #pragma unroll 4
    for (int i = 0; i < LC; i++) {
        size_t off = base + (size_t)i * U3;
        float rr = g_rkv[off + c];
        float kk = g_rkv[off + UD + c];
        float kv = g_rkv[off + 2 * UD + c];
        y1 = fmaf(y1, lam, kv);
        y2 = fmaf(y2, lam, kk);
        float r = 1.f / (1.f + expf(-rr));
        float x = (y1 + gamma * kv) / (y2 + gamma * kk + 1e-6f) * r;
        g_x[xbase + (size_t)i * UD + c] = x;
    }
}

// ---------------------------------------------------------------------------
// Launch
// ---------------------------------------------------------------------------
extern "C" void kernel_launch(void* const* d_in, const int* in_sizes, int n_in,
                              void* d_out, int out_size)
{
    const float* inputs    = (const float*)d_in[0];
    const float* W_rkv     = (const float*)d_in[1];
    const float* b_rkv     = (const float*)d_in[2];
    const float* W_o       = (const float*)d_in[3];
    const float* b_o       = (const float*)d_in[4];
    const float* nu_log    = (const float*)d_in[5];
    const float* gamma_log = (const float*)d_in[6];
    float* out = (float*)d_out;

    float *p_rkv = nullptr, *p_x = nullptr;
    __nv_bfloat16 *p_Ah = nullptr, *p_Xh = nullptr, *p_B1 = nullptr, *p_B2 = nullptr;
    cudaGetSymbolAddress((void**)&p_rkv, g_rkv);
    cudaGetSymbolAddress((void**)&p_x, g_x);
    cudaGetSymbolAddress((void**)&p_Ah, g_Ah);
    cudaGetSymbolAddress((void**)&p_Xh, g_Xh);
    cudaGetSymbolAddress((void**)&p_B1, g_B1);
    cudaGetSymbolAddress((void**)&p_B2, g_B2);

    static bool attr_set = false;
    if (!attr_set) {
        cudaFuncSetAttribute(gemm_mma, cudaFuncAttributeMaxDynamicSharedMemorySize, SMEM_GEMM);
        attr_set = true;
    }

    // Operand conversion (hi/lo bf16 split; B transposed to K-major [N, 2K])
    split_rows<<<(MROWS * 256 + 255) / 256, 256>>>(inputs, p_Ah, MROWS * 256);
    split_T<<<dim3(U3 / 32, HD / 32), dim3(32, 8)>>>(W_rkv, p_B1, HD, U3);
    split_T<<<dim3(HD / 32, UD / 32), dim3(32, 8)>>>(W_o, p_B2, UD, HD);

    // GEMM1: rkv = inputs @ W_rkv + b_rkv   [16384, 3072]
    gemm_mma<<<dim3(U3 / 256, MROWS / 128), 256, SMEM_GEMM>>>(p_Ah, p_B1, b_rkv, p_rkv, U3);

    // Scan
    scan_phaseA<<<dim3(UD / 256, NCHUNK, BB), 256>>>(nu_log);
    scan_phaseB<<<dim3(UD / 256, BB), 256>>>(nu_log);
    scan_phaseC<<<dim3(UD / 256, NCHUNK, BB), 256>>>(nu_log, gamma_log);

    // GEMM2: out = x @ W_o + b_o   [16384, 1024]
    split_rows<<<(MROWS * 256 + 255) / 256, 256>>>(p_x, p_Xh, MROWS * 256);
    gemm_mma<<<dim3(HD / 256, MROWS / 128), 256, SMEM_GEMM>>>(p_Xh, p_B2, b_o, out, HD);
}

// round 7
// speedup vs baseline: 2.0421x; 2.0421x over previous
#include <cuda_runtime.h>
#include <cuda_bf16.h>
#include <math.h>
#include <stdint.h>

// Problem constants
#define BB   4
#define LSEQ 4096
#define HD   1024
#define UD   1024
#define U3   3072
#define NCHUNK 64
#define LC     64
#define K2   2048           // stored split K: [hi | lo]
#define MROWS (BB*LSEQ)     // 16384

// Scratch (allocation-free: __device__ globals)
__device__ float g_rkv[(size_t)BB * LSEQ * U3];        // 192 MB fp32
__device__ float g_x[(size_t)BB * LSEQ * UD];          // 64 MB
__device__ float g_part[(size_t)BB * NCHUNK * 2 * UD]; // 2 MB
__device__ __nv_bfloat16 g_Ah[(size_t)MROWS * K2];     // 64 MB: split(inputs)
__device__ __nv_bfloat16 g_Xh[(size_t)MROWS * K2];     // 64 MB: split(x)
__device__ __nv_bfloat16 g_B1[(size_t)U3 * K2];        // 12 MB: split+T(W_rkv)
__device__ __nv_bfloat16 g_B2[(size_t)HD * K2];        //  4 MB: split+T(W_o)

__device__ __forceinline__ void cpa16(void* s, const void* g) {
    uint32_t sa = (uint32_t)__cvta_generic_to_shared(s);
    asm volatile("cp.async.cg.shared.global [%0], [%1], 16;" :: "r"(sa), "l"(g));
}

// ---------------------------------------------------------------------------
// bf16 warp-MMA GEMM (mma.sync m16n8k16, fp32 accum), 3-term hi/lo split:
//   C = A_hi*B_hi + A_hi*B_lo + A_lo*B_hi   (~fp32 accuracy)
// 96 virtual K-chunks of 32. CTA tile 128x128 with 4 warps (2x2),
// warp tile 64x64 -> MMA:LDSM = 4:1, 128 threads, 2 CTAs/SM (regfile fits).
// 3-stage cp.async pipeline (1 barrier/chunk), ldmatrix.x4 for A and B.
// SMEM rows padded to 40 bf16 (80B): 16B-aligned, conflict-free ldmatrix.
// ---------------------------------------------------------------------------
#define RS    40                // row stride (bf16 elems)
#define ATEL  (128 * RS)        // A tile elems
#define BTEL  (128 * RS)        // B tile elems
#define SEL   (ATEL + BTEL)     // elems per stage
#define STB   (SEL * 2)         // bytes per stage (20480)
#define SMEM_GEMM (3 * STB)     // 61440 bytes

__global__ void __launch_bounds__(128, 2) gemm_mma(
    const __nv_bfloat16* __restrict__ A,
    const __nv_bfloat16* __restrict__ Bt,
    const float* __restrict__ bias,
    float* __restrict__ C, int N)
{
    extern __shared__ __nv_bfloat16 smbuf[];
    const uint32_t smem0 = (uint32_t)__cvta_generic_to_shared(smbuf);

    const int tid  = threadIdx.x;
    const int m0   = blockIdx.y * 128;
    const int n0   = blockIdx.x * 128;
    const int warp = tid >> 5;
    const int lane = tid & 31;
    const int wm   = (warp >> 1) * 64;   // 0 or 64
    const int wn   = (warp & 1) * 64;    // 0 or 64
    const int gm   = lane >> 2;          // 0..7
    const int kq   = (lane & 3) * 2;     // 0,2,4,6

    // ldmatrix.x4 per-lane base offsets (bytes, within a stage)
    // A (m16 x k16): matrices ordered m-half, m-half+8, then k-half
    const uint32_t aOff = (uint32_t)(((wm + (lane & 7) + ((lane >> 3) & 1) * 8) * RS
                                      + (lane >> 4) * 8) * 2);
    // B (two n8 blocks x k16): matrices ordered k-half first, then n-half
    const uint32_t bOff = (uint32_t)(ATEL * 2 +
                                     ((wn + (lane & 7) + ((lane >> 4) & 1) * 8) * RS
                                      + ((lane >> 3) & 1) * 8) * 2);

    float acc[4][8][4];
    #pragma unroll
    for (int i = 0; i < 4; i++)
        #pragma unroll
        for (int j = 0; j < 8; j++)
            #pragma unroll
            for (int t = 0; t < 4; t++)
                acc[i][j][t] = 0.f;

    // loader: virtual chunk ci (0..95) -> stage st. 128 threads, 8 x 16B each.
    const int lr = tid >> 2;        // 0..31 base row
    const int lj = (tid & 3) * 8;   // 16B segment within 64B row-chunk
    auto load_chunk = [&](int ci, int st) {
        const int s   = ci >> 5;            // segment 0,1,2
        const int kof = (ci & 31) << 5;     // 0..992
        const size_t kA = (size_t)((s == 2) ? 1024 : 0) + kof;   // A: hi,hi,lo
        const size_t kB = (size_t)((s == 1) ? 1024 : 0) + kof;   // B: hi,lo,hi
        __nv_bfloat16* As = smbuf + (size_t)st * SEL;
        __nv_bfloat16* Bs = As + ATEL;
        #pragma unroll
        for (int h = 0; h < 4; h++) {
            int r = lr + h * 32;
            cpa16(As + r * RS + lj, A  + (size_t)(m0 + r) * K2 + kA + lj);
            cpa16(Bs + r * RS + lj, Bt + (size_t)(n0 + r) * K2 + kB + lj);
        }
        asm volatile("cp.async.commit_group;");
    };

    load_chunk(0, 0);
    load_chunk(1, 1);

    const int NCH = 96;
    for (int ci = 0; ci < NCH; ci++) {
        const int st = ci % 3;
        if (ci < NCH - 1) {
            asm volatile("cp.async.wait_group 1;" ::: "memory");
        } else {
            asm volatile("cp.async.wait_group 0;" ::: "memory");
        }
        __syncthreads();
        if (ci + 2 < NCH) load_chunk(ci + 2, (ci + 2) % 3);

        const uint32_t aBase = smem0 + (uint32_t)st * STB + aOff;
        const uint32_t bBase = smem0 + (uint32_t)st * STB + bOff;

        #pragma unroll
        for (int kk = 0; kk < 2; kk++) {
            uint32_t af[4][4], bf[8][2];
            #pragma unroll
            for (int i = 0; i < 4; i++)
                asm volatile(
                    "ldmatrix.sync.aligned.m8n8.x4.shared.b16 {%0,%1,%2,%3}, [%4];"
                    : "=r"(af[i][0]), "=r"(af[i][1]), "=r"(af[i][2]), "=r"(af[i][3])
                    : "r"(aBase + (uint32_t)(i * 16 * RS * 2 + kk * 32)));
            #pragma unroll
            for (int j = 0; j < 4; j++)
                asm volatile(
                    "ldmatrix.sync.aligned.m8n8.x4.shared.b16 {%0,%1,%2,%3}, [%4];"
                    : "=r"(bf[2*j][0]), "=r"(bf[2*j][1]),
                      "=r"(bf[2*j+1][0]), "=r"(bf[2*j+1][1])
                    : "r"(bBase + (uint32_t)(j * 16 * RS * 2 + kk * 32)));
            #pragma unroll
            for (int i = 0; i < 4; i++)
                #pragma unroll
                for (int j = 0; j < 8; j++)
                    asm volatile(
                        "mma.sync.aligned.m16n8k16.row.col.f32.bf16.bf16.f32 "
                        "{%0,%1,%2,%3}, {%4,%5,%6,%7}, {%8,%9}, {%0,%1,%2,%3};"
                        : "+f"(acc[i][j][0]), "+f"(acc[i][j][1]),
                          "+f"(acc[i][j][2]), "+f"(acc[i][j][3])
                        : "r"(af[i][0]), "r"(af[i][1]), "r"(af[i][2]), "r"(af[i][3]),
                          "r"(bf[j][0]), "r"(bf[j][1]));
        }
    }

    // Epilogue: bias + store (float2 per fragment row)
    #pragma unroll
    for (int j = 0; j < 8; j++) {
        const int col = n0 + wn + j * 8 + kq;
        const float b0 = bias[col], b1 = bias[col + 1];
        #pragma unroll
        for (int i = 0; i < 4; i++) {
            const int row = m0 + wm + i * 16 + gm;
            float2 v0 = make_float2(acc[i][j][0] + b0, acc[i][j][1] + b1);
            float2 v1 = make_float2(acc[i][j][2] + b0, acc[i][j][3] + b1);
            *(float2*)&C[(size_t)row * N + col]       = v0;
            *(float2*)&C[(size_t)(row + 8) * N + col] = v1;
        }
    }
}

// ---------------------------------------------------------------------------
// fp32 -> bf16 hi/lo split, row layout [R,1024] -> [R,2048] ([hi|lo])
// ---------------------------------------------------------------------------
__global__ void __launch_bounds__(256) split_rows(const float* __restrict__ X,
                                                  __nv_bfloat16* __restrict__ Y, int total4)
{
    int idx = blockIdx.x * 256 + threadIdx.x;
    if (idx >= total4) return;
    int r = idx >> 8;          // 256 float4 per row (K=1024)
    int c4 = idx & 255;
    float4 v = ((const float4*)X)[idx];
    float f[4] = { v.x, v.y, v.z, v.w };
    ushort4 hv, lv;
    unsigned short* hp = &hv.x; unsigned short* lp = &lv.x;
    #pragma unroll
    for (int i = 0; i < 4; i++) {
        __nv_bfloat16 h = __float2bfloat16(f[i]);
        __nv_bfloat16 l = __float2bfloat16(f[i] - __bfloat162float(h));
        hp[i] = __bfloat16_as_ushort(h);
        lp[i] = __bfloat16_as_ushort(l);
    }
    size_t o = (size_t)r * K2 + (c4 << 2);
    *(ushort4*)((unsigned short*)Y + o)         = hv;
    *(ushort4*)((unsigned short*)Y + o + 1024)  = lv;
}

// ---------------------------------------------------------------------------
// W[K,N] fp32 -> Bt[N,2048] bf16 (transpose + split), tiled 32x32
// ---------------------------------------------------------------------------
__global__ void split_T(const float* __restrict__ W, __nv_bfloat16* __restrict__ Bt,
                        int Kdim, int Ncols)
{
    __shared__ float t[32][33];
    int n = blockIdx.x * 32 + threadIdx.x;
    int k0 = blockIdx.y * 32;
    for (int i = threadIdx.y; i < 32; i += 8)
        t[i][threadIdx.x] = W[(size_t)(k0 + i) * Ncols + n];
    __syncthreads();
    int k = k0 + threadIdx.x;
    for (int i = threadIdx.y; i < 32; i += 8) {
        int nn = blockIdx.x * 32 + i;
        float v = t[threadIdx.x][i];
        __nv_bfloat16 h = __float2bfloat16(v);
        __nv_bfloat16 l = __float2bfloat16(v - __bfloat162float(h));
        Bt[(size_t)nn * K2 + k]        = h;
        Bt[(size_t)nn * K2 + 1024 + k] = l;
    }
}

// ---------------------------------------------------------------------------
// Chunked linear-recurrence scan (3 phases)
// ---------------------------------------------------------------------------
__global__ void __launch_bounds__(256) scan_phaseA(const float* __restrict__ nu_log)
{
    const int c = blockIdx.x * blockDim.x + threadIdx.x;
    const int chunk = blockIdx.y;
    const int b = blockIdx.z;
    const float lam = expf(-expf(nu_log[c]));

    size_t base = ((size_t)b * LSEQ + (size_t)chunk * LC) * U3;
    float y1 = 0.f, y2 = 0.f;
    #pragma unroll 4
    for (int i = 0; i < LC; i++) {
        size_t off = base + (size_t)i * U3;
        float kr = g_rkv[off + UD + c];
        float vr = g_rkv[off + 2 * UD + c];
        float kk = expf(kr);
        float kv = kk * vr;
        g_rkv[off + UD + c]     = kk;
        g_rkv[off + 2 * UD + c] = kv;
        y1 = fmaf(y1, lam, kv);
        y2 = fmaf(y2, lam, kk);
    }
    size_t p = (size_t)(b * NCHUNK + chunk) * 2 * UD + c;
    g_part[p]      = y1;
    g_part[p + UD] = y2;
}

__global__ void __launch_bounds__(256) scan_phaseB(const float* __restrict__ nu_log)
{
    const int c = blockIdx.x * blockDim.x + threadIdx.x;
    const int b = blockIdx.y;
    const float lam = expf(-expf(nu_log[c]));
    const float lamLc = powf(lam, (float)LC);
    float Y1 = 0.f, Y2 = 0.f;
    for (int j = 0; j < NCHUNK; j++) {
        size_t p = (size_t)(b * NCHUNK + j) * 2 * UD + c;
        float S1 = g_part[p], S2 = g_part[p + UD];
        g_part[p]      = Y1;
        g_part[p + UD] = Y2;
        Y1 = fmaf(Y1, lamLc, S1);
        Y2 = fmaf(Y2, lamLc, S2);
    }
}

__global__ void __launch_bounds__(256) scan_phaseC(const float* __restrict__ nu_log,
                                                   const float* __restrict__ gamma_log)
{
    const int c = blockIdx.x * blockDim.x + threadIdx.x;
    const int chunk = blockIdx.y;
    const int b = blockIdx.z;
    const float lam = expf(-expf(nu_log[c]));
    const float gamma = expf(nu_log[c] + gamma_log[c]) - 1.f;

    size_t p = (size_t)(b * NCHUNK + chunk) * 2 * UD + c;
    float y1 = g_part[p];
    float y2 = g_part[p + UD];

    size_t base  = ((size_t)b * LSEQ + (size_t)chunk * LC) * U3;
    size_t xbase = ((size_t)b * LSEQ + (size_t)chunk * LC) * UD;
    #pragma unroll 4
    for (int i = 0; i < LC; i++) {
        size_t off = base + (size_t)i * U3;
        float rr = g_rkv[off + c];
        float kk = g_rkv[off + UD + c];
        float kv = g_rkv[off + 2 * UD + c];
        y1 = fmaf(y1, lam, kv);
        y2 = fmaf(y2, lam, kk);
        float r = 1.f / (1.f + expf(-rr));
        float x = (y1 + gamma * kv) / (y2 + gamma * kk + 1e-6f) * r;
        g_x[xbase + (size_t)i * UD + c] = x;
    }
}

// ---------------------------------------------------------------------------
// Launch
// ---------------------------------------------------------------------------
extern "C" void kernel_launch(void* const* d_in, const int* in_sizes, int n_in,
                              void* d_out, int out_size)
{
    const float* inputs    = (const float*)d_in[0];
    const float* W_rkv     = (const float*)d_in[1];
    const float* b_rkv     = (const float*)d_in[2];
    const float* W_o       = (const float*)d_in[3];
    const float* b_o       = (const float*)d_in[4];
    const float* nu_log    = (const float*)d_in[5];
    const float* gamma_log = (const float*)d_in[6];
    float* out = (float*)d_out;

    float *p_rkv = nullptr, *p_x = nullptr;
    __nv_bfloat16 *p_Ah = nullptr, *p_Xh = nullptr, *p_B1 = nullptr, *p_B2 = nullptr;
    cudaGetSymbolAddress((void**)&p_rkv, g_rkv);
    cudaGetSymbolAddress((void**)&p_x, g_x);
    cudaGetSymbolAddress((void**)&p_Ah, g_Ah);
    cudaGetSymbolAddress((void**)&p_Xh, g_Xh);
    cudaGetSymbolAddress((void**)&p_B1, g_B1);
    cudaGetSymbolAddress((void**)&p_B2, g_B2);

    static bool attr_set = false;
    if (!attr_set) {
        cudaFuncSetAttribute(gemm_mma, cudaFuncAttributeMaxDynamicSharedMemorySize, SMEM_GEMM);
        attr_set = true;
    }

    // Operand conversion (hi/lo bf16 split; B transposed to K-major [N, 2K])
    split_rows<<<(MROWS * 256 + 255) / 256, 256>>>(inputs, p_Ah, MROWS * 256);
    split_T<<<dim3(U3 / 32, HD / 32), dim3(32, 8)>>>(W_rkv, p_B1, HD, U3);
    split_T<<<dim3(HD / 32, UD / 32), dim3(32, 8)>>>(W_o, p_B2, UD, HD);

    // GEMM1: rkv = inputs @ W_rkv + b_rkv   [16384, 3072]
    gemm_mma<<<dim3(U3 / 128, MROWS / 128), 128, SMEM_GEMM>>>(p_Ah, p_B1, b_rkv, p_rkv, U3);

    // Scan
    scan_phaseA<<<dim3(UD / 256, NCHUNK, BB), 256>>>(nu_log);
    scan_phaseB<<<dim3(UD / 256, BB), 256>>>(nu_log);
    scan_phaseC<<<dim3(UD / 256, NCHUNK, BB), 256>>>(nu_log, gamma_log);

    // GEMM2: out = x @ W_o + b_o   [16384, 1024]
    split_rows<<<(MROWS * 256 + 255) / 256, 256>>>(p_x, p_Xh, MROWS * 256);
    gemm_mma<<<dim3(HD / 128, MROWS / 128), 128, SMEM_GEMM>>>(p_Xh, p_B2, b_o, out, HD);
}

// round 8
// speedup vs baseline: 2.0607x; 1.0091x over previous
#include <cuda_runtime.h>
#include <cuda_bf16.h>
#include <math.h>
#include <stdint.h>

// Problem constants
#define BB   4
#define LSEQ 4096
#define HD   1024
#define UD   1024
#define U3   3072
#define NCHUNK 64
#define LC     64
#define K2   2048           // stored split K: [hi | lo]
#define MROWS (BB*LSEQ)     // 16384

// Scratch (allocation-free: __device__ globals)
__device__ float g_rkv[(size_t)BB * LSEQ * U3];        // 192 MB fp32
__device__ float g_x[(size_t)BB * LSEQ * UD];          // 64 MB
__device__ float g_part[(size_t)BB * NCHUNK * 2 * UD]; // 2 MB
__device__ __nv_bfloat16 g_Ah[(size_t)MROWS * K2];     // 64 MB: split(inputs)
__device__ __nv_bfloat16 g_Xh[(size_t)MROWS * K2];     // 64 MB: split(x)
__device__ __nv_bfloat16 g_B1[(size_t)U3 * K2];        // 12 MB: split+T(W_rkv)
__device__ __nv_bfloat16 g_B2[(size_t)HD * K2];        //  4 MB: split+T(W_o)

__device__ __forceinline__ void cpa16(void* s, const void* g) {
    uint32_t sa = (uint32_t)__cvta_generic_to_shared(s);
    asm volatile("cp.async.cg.shared.global [%0], [%1], 16;" :: "r"(sa), "l"(g));
}

// ---------------------------------------------------------------------------
// bf16 warp-MMA GEMM (mma.sync m16n8k16, fp32 accum), 3-term hi/lo split
// with TERM SHARING: each k32 chunk loads (A_hi, A_lo, B_hi, B_lo) once and
// computes A_hi*B_hi + A_lo*B_hi + A_hi*B_lo from the same SMEM data.
// 32 chunks. CTA tile 128x128, 4 warps (2x2), warp tile 64x64.
// 2-stage cp.async pipeline (1 barrier/chunk), ldmatrix.x4, B-reg reuse.
// SMEM rows padded to 40 bf16 (80B): 16B-aligned, conflict-free ldmatrix.
// ---------------------------------------------------------------------------
#define RS    40                // row stride (bf16 elems)
#define TEL   (128 * RS)        // one tile (128 rows) elems
#define SEL   (4 * TEL)         // stage: Ahi, Alo, Bhi, Blo
#define STB   (SEL * 2)         // bytes per stage (40960)
#define SMEM_GEMM (2 * STB)     // 81920 bytes

__global__ void __launch_bounds__(128, 2) gemm_mma(
    const __nv_bfloat16* __restrict__ A,
    const __nv_bfloat16* __restrict__ Bt,
    const float* __restrict__ bias,
    float* __restrict__ C, int N)
{
    extern __shared__ __nv_bfloat16 smbuf[];
    const uint32_t smem0 = (uint32_t)__cvta_generic_to_shared(smbuf);

    const int tid  = threadIdx.x;
    const int m0   = blockIdx.y * 128;
    const int n0   = blockIdx.x * 128;
    const int warp = tid >> 5;
    const int lane = tid & 31;
    const int wm   = (warp >> 1) * 64;   // 0 or 64
    const int wn   = (warp & 1) * 64;    // 0 or 64
    const int gm   = lane >> 2;          // 0..7
    const int kq   = (lane & 3) * 2;     // 0,2,4,6

    // ldmatrix.x4 per-lane offsets (bytes, within one tile)
    // A (m16 x k16): matrices ordered m-half, m-half+8, then k-half
    const uint32_t aOff = (uint32_t)(((wm + (lane & 7) + ((lane >> 3) & 1) * 8) * RS
                                      + (lane >> 4) * 8) * 2);
    // B (two n8 blocks x k16): matrices ordered k-half first, then n-half
    const uint32_t bOff = (uint32_t)(((wn + (lane & 7) + ((lane >> 4) & 1) * 8) * RS
                                      + ((lane >> 3) & 1) * 8) * 2);

    float acc[4][8][4];
    #pragma unroll
    for (int i = 0; i < 4; i++)
        #pragma unroll
        for (int j = 0; j < 8; j++)
            #pragma unroll
            for (int t = 0; t < 4; t++)
                acc[i][j][t] = 0.f;

    // loader: chunk ci (0..31) -> stage st. 128 threads, 16 x 16B each.
    const int lr = tid >> 2;        // 0..31 base row
    const int lj = (tid & 3) * 8;   // 16B segment within 64B row-chunk
    auto load_chunk = [&](int ci, int st) {
        const size_t kof = (size_t)(ci << 5);
        __nv_bfloat16* Ah = smbuf + (size_t)st * SEL;
        __nv_bfloat16* Al = Ah + TEL;
        __nv_bfloat16* Bh = Al + TEL;
        __nv_bfloat16* Bl = Bh + TEL;
        #pragma unroll
        for (int h = 0; h < 4; h++) {
            int r = lr + h * 32;
            const __nv_bfloat16* ga = A  + (size_t)(m0 + r) * K2 + kof + lj;
            const __nv_bfloat16* gb = Bt + (size_t)(n0 + r) * K2 + kof + lj;
            cpa16(Ah + r * RS + lj, ga);
            cpa16(Al + r * RS + lj, ga + 1024);
            cpa16(Bh + r * RS + lj, gb);
            cpa16(Bl + r * RS + lj, gb + 1024);
        }
        asm volatile("cp.async.commit_group;");
    };

    load_chunk(0, 0);

    const int NCH = 32;
    for (int ci = 0; ci < NCH; ci++) {
        const int st = ci & 1;
        asm volatile("cp.async.wait_group 0;" ::: "memory");
        __syncthreads();
        if (ci + 1 < NCH) load_chunk(ci + 1, st ^ 1);

        const uint32_t base  = smem0 + (uint32_t)st * STB;
        const uint32_t aBaseH = base + aOff;
        const uint32_t aBaseL = base + (uint32_t)(TEL * 2) + aOff;
        const uint32_t bBaseH = base + (uint32_t)(2 * TEL * 2) + bOff;
        const uint32_t bBaseL = base + (uint32_t)(3 * TEL * 2) + bOff;

        #pragma unroll
        for (int kk = 0; kk < 2; kk++) {
            uint32_t afh[4][4], afl[4][4], bf[8][2];
            #pragma unroll
            for (int i = 0; i < 4; i++)
                asm volatile(
                    "ldmatrix.sync.aligned.m8n8.x4.shared.b16 {%0,%1,%2,%3}, [%4];"
                    : "=r"(afh[i][0]), "=r"(afh[i][1]), "=r"(afh[i][2]), "=r"(afh[i][3])
                    : "r"(aBaseH + (uint32_t)(i * 16 * RS * 2 + kk * 32)));
            #pragma unroll
            for (int i = 0; i < 4; i++)
                asm volatile(
                    "ldmatrix.sync.aligned.m8n8.x4.shared.b16 {%0,%1,%2,%3}, [%4];"
                    : "=r"(afl[i][0]), "=r"(afl[i][1]), "=r"(afl[i][2]), "=r"(afl[i][3])
                    : "r"(aBaseL + (uint32_t)(i * 16 * RS * 2 + kk * 32)));
            // ---- B_hi: acc += A_hi*B_hi + A_lo*B_hi ----
            #pragma unroll
            for (int j = 0; j < 4; j++)
                asm volatile(
                    "ldmatrix.sync.aligned.m8n8.x4.shared.b16 {%0,%1,%2,%3}, [%4];"
                    : "=r"(bf[2*j][0]), "=r"(bf[2*j][1]),
                      "=r"(bf[2*j+1][0]), "=r"(bf[2*j+1][1])
                    : "r"(bBaseH + (uint32_t)(j * 16 * RS * 2 + kk * 32)));
            #pragma unroll
            for (int i = 0; i < 4; i++)
                #pragma unroll
                for (int j = 0; j < 8; j++)
                    asm volatile(
                        "mma.sync.aligned.m16n8k16.row.col.f32.bf16.bf16.f32 "
                        "{%0,%1,%2,%3}, {%4,%5,%6,%7}, {%8,%9}, {%0,%1,%2,%3};"
                        : "+f"(acc[i][j][0]), "+f"(acc[i][j][1]),
                          "+f"(acc[i][j][2]), "+f"(acc[i][j][3])
                        : "r"(afh[i][0]), "r"(afh[i][1]), "r"(afh[i][2]), "r"(afh[i][3]),
                          "r"(bf[j][0]), "r"(bf[j][1]));
            #pragma unroll
            for (int i = 0; i < 4; i++)
                #pragma unroll
                for (int j = 0; j < 8; j++)
                    asm volatile(
                        "mma.sync.aligned.m16n8k16.row.col.f32.bf16.bf16.f32 "
                        "{%0,%1,%2,%3}, {%4,%5,%6,%7}, {%8,%9}, {%0,%1,%2,%3};"
                        : "+f"(acc[i][j][0]), "+f"(acc[i][j][1]),
                          "+f"(acc[i][j][2]), "+f"(acc[i][j][3])
                        : "r"(afl[i][0]), "r"(afl[i][1]), "r"(afl[i][2]), "r"(afl[i][3]),
                          "r"(bf[j][0]), "r"(bf[j][1]));
            // ---- B_lo: acc += A_hi*B_lo ----
            #pragma unroll
            for (int j = 0; j < 4; j++)
                asm volatile(
                    "ldmatrix.sync.aligned.m8n8.x4.shared.b16 {%0,%1,%2,%3}, [%4];"
                    : "=r"(bf[2*j][0]), "=r"(bf[2*j][1]),
                      "=r"(bf[2*j+1][0]), "=r"(bf[2*j+1][1])
                    : "r"(bBaseL + (uint32_t)(j * 16 * RS * 2 + kk * 32)));
            #pragma unroll
            for (int i = 0; i < 4; i++)
                #pragma unroll
                for (int j = 0; j < 8; j++)
                    asm volatile(
                        "mma.sync.aligned.m16n8k16.row.col.f32.bf16.bf16.f32 "
                        "{%0,%1,%2,%3}, {%4,%5,%6,%7}, {%8,%9}, {%0,%1,%2,%3};"
                        : "+f"(acc[i][j][0]), "+f"(acc[i][j][1]),
                          "+f"(acc[i][j][2]), "+f"(acc[i][j][3])
                        : "r"(afh[i][0]), "r"(afh[i][1]), "r"(afh[i][2]), "r"(afh[i][3]),
                          "r"(bf[j][0]), "r"(bf[j][1]));
        }
    }

    // Epilogue: bias + store (float2 per fragment row)
    #pragma unroll
    for (int j = 0; j < 8; j++) {
        const int col = n0 + wn + j * 8 + kq;
        const float b0 = bias[col], b1 = bias[col + 1];
        #pragma unroll
        for (int i = 0; i < 4; i++) {
            const int row = m0 + wm + i * 16 + gm;
            float2 v0 = make_float2(acc[i][j][0] + b0, acc[i][j][1] + b1);
            float2 v1 = make_float2(acc[i][j][2] + b0, acc[i][j][3] + b1);
            *(float2*)&C[(size_t)row * N + col]       = v0;
            *(float2*)&C[(size_t)(row + 8) * N + col] = v1;
        }
    }
}

// ---------------------------------------------------------------------------
// fp32 -> bf16 hi/lo split, row layout [R,1024] -> [R,2048] ([hi|lo])
// ---------------------------------------------------------------------------
__global__ void __launch_bounds__(256) split_rows(const float* __restrict__ X,
                                                  __nv_bfloat16* __restrict__ Y, int total4)
{
    int idx = blockIdx.x * 256 + threadIdx.x;
    if (idx >= total4) return;
    int r = idx >> 8;          // 256 float4 per row (K=1024)
    int c4 = idx & 255;
    float4 v = ((const float4*)X)[idx];
    float f[4] = { v.x, v.y, v.z, v.w };
    ushort4 hv, lv;
    unsigned short* hp = &hv.x; unsigned short* lp = &lv.x;
    #pragma unroll
    for (int i = 0; i < 4; i++) {
        __nv_bfloat16 h = __float2bfloat16(f[i]);
        __nv_bfloat16 l = __float2bfloat16(f[i] - __bfloat162float(h));
        hp[i] = __bfloat16_as_ushort(h);
        lp[i] = __bfloat16_as_ushort(l);
    }
    size_t o = (size_t)r * K2 + (c4 << 2);
    *(ushort4*)((unsigned short*)Y + o)         = hv;
    *(ushort4*)((unsigned short*)Y + o + 1024)  = lv;
}

// ---------------------------------------------------------------------------
// W[K,N] fp32 -> Bt[N,2048] bf16 (transpose + split), tiled 32x32
// ---------------------------------------------------------------------------
__global__ void split_T(const float* __restrict__ W, __nv_bfloat16* __restrict__ Bt,
                        int Kdim, int Ncols)
{
    __shared__ float t[32][33];
    int n = blockIdx.x * 32 + threadIdx.x;
    int k0 = blockIdx.y * 32;
    for (int i = threadIdx.y; i < 32; i += 8)
        t[i][threadIdx.x] = W[(size_t)(k0 + i) * Ncols + n];
    __syncthreads();
    int k = k0 + threadIdx.x;
    for (int i = threadIdx.y; i < 32; i += 8) {
        int nn = blockIdx.x * 32 + i;
        float v = t[threadIdx.x][i];
        __nv_bfloat16 h = __float2bfloat16(v);
        __nv_bfloat16 l = __float2bfloat16(v - __bfloat162float(h));
        Bt[(size_t)nn * K2 + k]        = h;
        Bt[(size_t)nn * K2 + 1024 + k] = l;
    }
}

// ---------------------------------------------------------------------------
// Chunked linear-recurrence scan (3 phases)
// ---------------------------------------------------------------------------
__global__ void __launch_bounds__(256) scan_phaseA(const float* __restrict__ nu_log)
{
    const int c = blockIdx.x * blockDim.x + threadIdx.x;
    const int chunk = blockIdx.y;
    const int b = blockIdx.z;
    const float lam = expf(-expf(nu_log[c]));

    size_t base = ((size_t)b * LSEQ + (size_t)chunk * LC) * U3;
    float y1 = 0.f, y2 = 0.f;
    #pragma unroll 4
    for (int i = 0; i < LC; i++) {
        size_t off = base + (size_t)i * U3;
        float kr = g_rkv[off + UD + c];
        float vr = g_rkv[off + 2 * UD + c];
        float kk = expf(kr);
        float kv = kk * vr;
        g_rkv[off + UD + c]     = kk;
        g_rkv[off + 2 * UD + c] = kv;
        y1 = fmaf(y1, lam, kv);
        y2 = fmaf(y2, lam, kk);
    }
    size_t p = (size_t)(b * NCHUNK + chunk) * 2 * UD + c;
    g_part[p]      = y1;
    g_part[p + UD] = y2;
}

__global__ void __launch_bounds__(256) scan_phaseB(const float* __restrict__ nu_log)
{
    const int c = blockIdx.x * blockDim.x + threadIdx.x;
    const int b = blockIdx.y;
    const float lam = expf(-expf(nu_log[c]));
    const float lamLc = powf(lam, (float)LC);
    float Y1 = 0.f, Y2 = 0.f;
    for (int j = 0; j < NCHUNK; j++) {
        size_t p = (size_t)(b * NCHUNK + j) * 2 * UD + c;
        float S1 = g_part[p], S2 = g_part[p + UD];
        g_part[p]      = Y1;
        g_part[p + UD] = Y2;
        Y1 = fmaf(Y1, lamLc, S1);
        Y2 = fmaf(Y2, lamLc, S2);
    }
}

__global__ void __launch_bounds__(256) scan_phaseC(const float* __restrict__ nu_log,
                                                   const float* __restrict__ gamma_log)
{
    const int c = blockIdx.x * blockDim.x + threadIdx.x;
    const int chunk = blockIdx.y;
    const int b = blockIdx.z;
    const float lam = expf(-expf(nu_log[c]));
    const float gamma = expf(nu_log[c] + gamma_log[c]) - 1.f;

    size_t p = (size_t)(b * NCHUNK + chunk) * 2 * UD + c;
    float y1 = g_part[p];
    float y2 = g_part[p + UD];

    size_t base  = ((size_t)b * LSEQ + (size_t)chunk * LC) * U3;
    size_t xbase = ((size_t)b * LSEQ + (size_t)chunk * LC) * UD;
    #pragma unroll 4
    for (int i = 0; i < LC; i++) {
        size_t off = base + (size_t)i * U3;
        float rr = g_rkv[off + c];
        float kk = g_rkv[off + UD + c];
        float kv = g_rkv[off + 2 * UD + c];
        y1 = fmaf(y1, lam, kv);
        y2 = fmaf(y2, lam, kk);
        float r = 1.f / (1.f + expf(-rr));
        float x = (y1 + gamma * kv) / (y2 + gamma * kk + 1e-6f) * r;
        g_x[xbase + (size_t)i * UD + c] = x;
    }
}

// ---------------------------------------------------------------------------
// Launch
// ---------------------------------------------------------------------------
extern "C" void kernel_launch(void* const* d_in, const int* in_sizes, int n_in,
                              void* d_out, int out_size)
{
    const float* inputs    = (const float*)d_in[0];
    const float* W_rkv     = (const float*)d_in[1];
    const float* b_rkv     = (const float*)d_in[2];
    const float* W_o       = (const float*)d_in[3];
    const float* b_o       = (const float*)d_in[4];
    const float* nu_log    = (const float*)d_in[5];
    const float* gamma_log = (const float*)d_in[6];
    float* out = (float*)d_out;

    float *p_rkv = nullptr, *p_x = nullptr;
    __nv_bfloat16 *p_Ah = nullptr, *p_Xh = nullptr, *p_B1 = nullptr, *p_B2 = nullptr;
    cudaGetSymbolAddress((void**)&p_rkv, g_rkv);
    cudaGetSymbolAddress((void**)&p_x, g_x);
    cudaGetSymbolAddress((void**)&p_Ah, g_Ah);
    cudaGetSymbolAddress((void**)&p_Xh, g_Xh);
    cudaGetSymbolAddress((void**)&p_B1, g_B1);
    cudaGetSymbolAddress((void**)&p_B2, g_B2);

    static bool attr_set = false;
    if (!attr_set) {
        cudaFuncSetAttribute(gemm_mma, cudaFuncAttributeMaxDynamicSharedMemorySize, SMEM_GEMM);
        attr_set = true;
    }

    // Operand conversion (hi/lo bf16 split; B transposed to K-major [N, 2K])
    split_rows<<<(MROWS * 256 + 255) / 256, 256>>>(inputs, p_Ah, MROWS * 256);
    split_T<<<dim3(U3 / 32, HD / 32), dim3(32, 8)>>>(W_rkv, p_B1, HD, U3);
    split_T<<<dim3(HD / 32, UD / 32), dim3(32, 8)>>>(W_o, p_B2, UD, HD);

    // GEMM1: rkv = inputs @ W_rkv + b_rkv   [16384, 3072]
    gemm_mma<<<dim3(U3 / 128, MROWS / 128), 128, SMEM_GEMM>>>(p_Ah, p_B1, b_rkv, p_rkv, U3);

    // Scan
    scan_phaseA<<<dim3(UD / 256, NCHUNK, BB), 256>>>(nu_log);
    scan_phaseB<<<dim3(UD / 256, BB), 256>>>(nu_log);
    scan_phaseC<<<dim3(UD / 256, NCHUNK, BB), 256>>>(nu_log, gamma_log);

    // GEMM2: out = x @ W_o + b_o   [16384, 1024]
    split_rows<<<(MROWS * 256 + 255) / 256, 256>>>(p_x, p_Xh, MROWS * 256);
    gemm_mma<<<dim3(HD / 128, MROWS / 128), 128, SMEM_GEMM>>>(p_Xh, p_B2, b_o, out, HD);
}

// round 9
// speedup vs baseline: 2.1077x; 1.0228x over previous
#include <cuda_runtime.h>
#include <cuda_bf16.h>
#include <math.h>
#include <stdint.h>

// Problem constants
#define BB   4
#define LSEQ 4096
#define HD   1024
#define UD   1024
#define U3   3072
#define NCHUNK 64
#define LC     64
#define K2   2048           // stored split K: [hi | lo]
#define MROWS (BB*LSEQ)     // 16384

// Scratch (allocation-free: __device__ globals)
__device__ float g_rkv[(size_t)BB * LSEQ * U3];        // 192 MB fp32
__device__ float g_x[(size_t)BB * LSEQ * UD];          // 64 MB
__device__ float g_part[(size_t)BB * NCHUNK * 2 * UD]; // 2 MB
__device__ __nv_bfloat16 g_Ah[(size_t)MROWS * K2];     // 64 MB: split(inputs)
__device__ __nv_bfloat16 g_Xh[(size_t)MROWS * K2];     // 64 MB: split(x)
__device__ __nv_bfloat16 g_B1[(size_t)U3 * K2];        // 12 MB: split+T(W_rkv)
__device__ __nv_bfloat16 g_B2[(size_t)HD * K2];        //  4 MB: split+T(W_o)

__device__ __forceinline__ void cpa16(void* s, const void* g) {
    uint32_t sa = (uint32_t)__cvta_generic_to_shared(s);
    asm volatile("cp.async.cg.shared.global [%0], [%1], 16;" :: "r"(sa), "l"(g));
}

// ---------------------------------------------------------------------------
// bf16 warp-MMA GEMM (mma.sync m16n8k16, fp32 accum), 3-term hi/lo split
// with TERM SHARING. Term order (Ahi*Bhi),(Alo*Bhi),(Ahi*Blo) lets B_lo
// overwrite B_hi registers.
// 32 k32-chunks. CTA tile 128x128, 8 warps (4m x 2n), warp tile 32x64,
// 256 threads, 2 CTAs/SM (16 warps/SM = 4/SMSP for latency hiding).
// 2-stage cp.async pipeline (1 barrier/chunk), ldmatrix.x4.
// SMEM rows padded to 40 bf16 (80B): 16B-aligned, conflict-free ldmatrix.
// ---------------------------------------------------------------------------
#define RS    40                // row stride (bf16 elems)
#define TEL   (128 * RS)        // one tile (128 rows) elems
#define SEL   (4 * TEL)         // stage: Ahi, Alo, Bhi, Blo
#define STB   (SEL * 2)         // bytes per stage (40960)
#define SMEM_GEMM (2 * STB)     // 81920 bytes

__global__ void __launch_bounds__(256, 2) gemm_mma(
    const __nv_bfloat16* __restrict__ A,
    const __nv_bfloat16* __restrict__ Bt,
    const float* __restrict__ bias,
    float* __restrict__ C, int N)
{
    extern __shared__ __nv_bfloat16 smbuf[];
    const uint32_t smem0 = (uint32_t)__cvta_generic_to_shared(smbuf);

    const int tid  = threadIdx.x;
    const int m0   = blockIdx.y * 128;
    const int n0   = blockIdx.x * 128;
    const int warp = tid >> 5;
    const int lane = tid & 31;
    const int wm   = (warp >> 1) * 32;   // 0,32,64,96
    const int wn   = (warp & 1) * 64;    // 0 or 64
    const int gm   = lane >> 2;          // 0..7
    const int kq   = (lane & 3) * 2;     // 0,2,4,6

    // ldmatrix.x4 per-lane offsets (bytes, within one tile)
    // A (m16 x k16): matrices ordered m-half, m-half+8, then k-half
    const uint32_t aOff = (uint32_t)(((wm + (lane & 7) + ((lane >> 3) & 1) * 8) * RS
                                      + (lane >> 4) * 8) * 2);
    // B (two n8 blocks x k16): matrices ordered k-half first, then n-half
    const uint32_t bOff = (uint32_t)(((wn + (lane & 7) + ((lane >> 4) & 1) * 8) * RS
                                      + ((lane >> 3) & 1) * 8) * 2);

    float acc[2][8][4];
    #pragma unroll
    for (int i = 0; i < 2; i++)
        #pragma unroll
        for (int j = 0; j < 8; j++)
            #pragma unroll
            for (int t = 0; t < 4; t++)
                acc[i][j][t] = 0.f;

    // loader: chunk ci (0..31) -> stage st. 256 threads, 8 x 16B each.
    const int lr = tid >> 2;        // 0..63 base row
    const int lj = (tid & 3) * 8;   // 16B segment within 64B row-chunk
    auto load_chunk = [&](int ci, int st) {
        const size_t kof = (size_t)(ci << 5);
        __nv_bfloat16* Ah = smbuf + (size_t)st * SEL;
        __nv_bfloat16* Al = Ah + TEL;
        __nv_bfloat16* Bh = Al + TEL;
        __nv_bfloat16* Bl = Bh + TEL;
        #pragma unroll
        for (int h = 0; h < 2; h++) {
            int r = lr + h * 64;
            const __nv_bfloat16* ga = A  + (size_t)(m0 + r) * K2 + kof + lj;
            const __nv_bfloat16* gb = Bt + (size_t)(n0 + r) * K2 + kof + lj;
            cpa16(Ah + r * RS + lj, ga);
            cpa16(Al + r * RS + lj, ga + 1024);
            cpa16(Bh + r * RS + lj, gb);
            cpa16(Bl + r * RS + lj, gb + 1024);
        }
        asm volatile("cp.async.commit_group;");
    };

    load_chunk(0, 0);

    const int NCH = 32;
    for (int ci = 0; ci < NCH; ci++) {
        const int st = ci & 1;
        asm volatile("cp.async.wait_group 0;" ::: "memory");
        __syncthreads();
        if (ci + 1 < NCH) load_chunk(ci + 1, st ^ 1);

        const uint32_t base   = smem0 + (uint32_t)st * STB;
        const uint32_t aBaseH = base + aOff;
        const uint32_t aBaseL = base + (uint32_t)(TEL * 2) + aOff;
        const uint32_t bBaseH = base + (uint32_t)(2 * TEL * 2) + bOff;
        const uint32_t bBaseL = base + (uint32_t)(3 * TEL * 2) + bOff;

        #pragma unroll
        for (int kk = 0; kk < 2; kk++) {
            uint32_t afh[2][4], afl[2][4], bf[8][2];
            #pragma unroll
            for (int i = 0; i < 2; i++)
                asm volatile(
                    "ldmatrix.sync.aligned.m8n8.x4.shared.b16 {%0,%1,%2,%3}, [%4];"
                    : "=r"(afh[i][0]), "=r"(afh[i][1]), "=r"(afh[i][2]), "=r"(afh[i][3])
                    : "r"(aBaseH + (uint32_t)(i * 16 * RS * 2 + kk * 32)));
            #pragma unroll
            for (int i = 0; i < 2; i++)
                asm volatile(
                    "ldmatrix.sync.aligned.m8n8.x4.shared.b16 {%0,%1,%2,%3}, [%4];"
                    : "=r"(afl[i][0]), "=r"(afl[i][1]), "=r"(afl[i][2]), "=r"(afl[i][3])
                    : "r"(aBaseL + (uint32_t)(i * 16 * RS * 2 + kk * 32)));
            // ---- B_hi: acc += A_hi*B_hi + A_lo*B_hi ----
            #pragma unroll
            for (int j = 0; j < 4; j++)
                asm volatile(
                    "ldmatrix.sync.aligned.m8n8.x4.shared.b16 {%0,%1,%2,%3}, [%4];"
                    : "=r"(bf[2*j][0]), "=r"(bf[2*j][1]),
                      "=r"(bf[2*j+1][0]), "=r"(bf[2*j+1][1])
                    : "r"(bBaseH + (uint32_t)(j * 16 * RS * 2 + kk * 32)));
            #pragma unroll
            for (int i = 0; i < 2; i++)
                #pragma unroll
                for (int j = 0; j < 8; j++)
                    asm volatile(
                        "mma.sync.aligned.m16n8k16.row.col.f32.bf16.bf16.f32 "
                        "{%0,%1,%2,%3}, {%4,%5,%6,%7}, {%8,%9}, {%0,%1,%2,%3};"
                        : "+f"(acc[i][j][0]), "+f"(acc[i][j][1]),
                          "+f"(acc[i][j][2]), "+f"(acc[i][j][3])
                        : "r"(afh[i][0]), "r"(afh[i][1]), "r"(afh[i][2]), "r"(afh[i][3]),
                          "r"(bf[j][0]), "r"(bf[j][1]));
            #pragma unroll
            for (int i = 0; i < 2; i++)
                #pragma unroll
                for (int j = 0; j < 8; j++)
                    asm volatile(
                        "mma.sync.aligned.m16n8k16.row.col.f32.bf16.bf16.f32 "
                        "{%0,%1,%2,%3}, {%4,%5,%6,%7}, {%8,%9}, {%0,%1,%2,%3};"
                        : "+f"(acc[i][j][0]), "+f"(acc[i][j][1]),
                          "+f"(acc[i][j][2]), "+f"(acc[i][j][3])
                        : "r"(afl[i][0]), "r"(afl[i][1]), "r"(afl[i][2]), "r"(afl[i][3]),
                          "r"(bf[j][0]), "r"(bf[j][1]));
            // ---- B_lo: acc += A_hi*B_lo (B_lo overwrites B_hi regs) ----
            #pragma unroll
            for (int j = 0; j < 4; j++)
                asm volatile(
                    "ldmatrix.sync.aligned.m8n8.x4.shared.b16 {%0,%1,%2,%3}, [%4];"
                    : "=r"(bf[2*j][0]), "=r"(bf[2*j][1]),
                      "=r"(bf[2*j+1][0]), "=r"(bf[2*j+1][1])
                    : "r"(bBaseL + (uint32_t)(j * 16 * RS * 2 + kk * 32)));
            #pragma unroll
            for (int i = 0; i < 2; i++)
                #pragma unroll
                for (int j = 0; j < 8; j++)
                    asm volatile(
                        "mma.sync.aligned.m16n8k16.row.col.f32.bf16.bf16.f32 "
                        "{%0,%1,%2,%3}, {%4,%5,%6,%7}, {%8,%9}, {%0,%1,%2,%3};"
                        : "+f"(acc[i][j][0]), "+f"(acc[i][j][1]),
                          "+f"(acc[i][j][2]), "+f"(acc[i][j][3])
                        : "r"(afh[i][0]), "r"(afh[i][1]), "r"(afh[i][2]), "r"(afh[i][3]),
                          "r"(bf[j][0]), "r"(bf[j][1]));
        }
    }

    // Epilogue: bias + store (float2 per fragment row)
    #pragma unroll
    for (int j = 0; j < 8; j++) {
        const int col = n0 + wn + j * 8 + kq;
        const float b0 = bias[col], b1 = bias[col + 1];
        #pragma unroll
        for (int i = 0; i < 2; i++) {
            const int row = m0 + wm + i * 16 + gm;
            float2 v0 = make_float2(acc[i][j][0] + b0, acc[i][j][1] + b1);
            float2 v1 = make_float2(acc[i][j][2] + b0, acc[i][j][3] + b1);
            *(float2*)&C[(size_t)row * N + col]       = v0;
            *(float2*)&C[(size_t)(row + 8) * N + col] = v1;
        }
    }
}

// ---------------------------------------------------------------------------
// fp32 -> bf16 hi/lo split, row layout [R,1024] -> [R,2048] ([hi|lo])
// ---------------------------------------------------------------------------
__global__ void __launch_bounds__(256) split_rows(const float* __restrict__ X,
                                                  __nv_bfloat16* __restrict__ Y, int total4)
{
    int idx = blockIdx.x * 256 + threadIdx.x;
    if (idx >= total4) return;
    int r = idx >> 8;          // 256 float4 per row (K=1024)
    int c4 = idx & 255;
    float4 v = ((const float4*)X)[idx];
    float f[4] = { v.x, v.y, v.z, v.w };
    ushort4 hv, lv;
    unsigned short* hp = &hv.x; unsigned short* lp = &lv.x;
    #pragma unroll
    for (int i = 0; i < 4; i++) {
        __nv_bfloat16 h = __float2bfloat16(f[i]);
        __nv_bfloat16 l = __float2bfloat16(f[i] - __bfloat162float(h));
        hp[i] = __bfloat16_as_ushort(h);
        lp[i] = __bfloat16_as_ushort(l);
    }
    size_t o = (size_t)r * K2 + (c4 << 2);
    *(ushort4*)((unsigned short*)Y + o)         = hv;
    *(ushort4*)((unsigned short*)Y + o + 1024)  = lv;
}

// ---------------------------------------------------------------------------
// W[K,N] fp32 -> Bt[N,2048] bf16 (transpose + split), tiled 32x32
// ---------------------------------------------------------------------------
__global__ void split_T(const float* __restrict__ W, __nv_bfloat16* __restrict__ Bt,
                        int Kdim, int Ncols)
{
    __shared__ float t[32][33];
    int n = blockIdx.x * 32 + threadIdx.x;
    int k0 = blockIdx.y * 32;
    for (int i = threadIdx.y; i < 32; i += 8)
        t[i][threadIdx.x] = W[(size_t)(k0 + i) * Ncols + n];
    __syncthreads();
    int k = k0 + threadIdx.x;
    for (int i = threadIdx.y; i < 32; i += 8) {
        int nn = blockIdx.x * 32 + i;
        float v = t[threadIdx.x][i];
        __nv_bfloat16 h = __float2bfloat16(v);
        __nv_bfloat16 l = __float2bfloat16(v - __bfloat162float(h));
        Bt[(size_t)nn * K2 + k]        = h;
        Bt[(size_t)nn * K2 + 1024 + k] = l;
    }
}

// ---------------------------------------------------------------------------
// Chunked linear-recurrence scan (3 phases)
// ---------------------------------------------------------------------------
__global__ void __launch_bounds__(256) scan_phaseA(const float* __restrict__ nu_log)
{
    const int c = blockIdx.x * blockDim.x + threadIdx.x;
    const int chunk = blockIdx.y;
    const int b = blockIdx.z;
    const float lam = expf(-expf(nu_log[c]));

    size_t base = ((size_t)b * LSEQ + (size_t)chunk * LC) * U3;
    float y1 = 0.f, y2 = 0.f;
    #pragma unroll 4
    for (int i = 0; i < LC; i++) {
        size_t off = base + (size_t)i * U3;
        float kr = g_rkv[off + UD + c];
        float vr = g_rkv[off + 2 * UD + c];
        float kk = expf(kr);
        float kv = kk * vr;
        g_rkv[off + UD + c]     = kk;
        g_rkv[off + 2 * UD + c] = kv;
        y1 = fmaf(y1, lam, kv);
        y2 = fmaf(y2, lam, kk);
    }
    size_t p = (size_t)(b * NCHUNK + chunk) * 2 * UD + c;
    g_part[p]      = y1;
    g_part[p + UD] = y2;
}

__global__ void __launch_bounds__(256) scan_phaseB(const float* __restrict__ nu_log)
{
    const int c = blockIdx.x * blockDim.x + threadIdx.x;
    const int b = blockIdx.y;
    const float lam = expf(-expf(nu_log[c]));
    const float lamLc = powf(lam, (float)LC);
    float Y1 = 0.f, Y2 = 0.f;
    for (int j = 0; j < NCHUNK; j++) {
        size_t p = (size_t)(b * NCHUNK + j) * 2 * UD + c;
        float S1 = g_part[p], S2 = g_part[p + UD];
        g_part[p]      = Y1;
        g_part[p + UD] = Y2;
        Y1 = fmaf(Y1, lamLc, S1);
        Y2 = fmaf(Y2, lamLc, S2);
    }
}

__global__ void __launch_bounds__(256) scan_phaseC(const float* __restrict__ nu_log,
                                                   const float* __restrict__ gamma_log)
{
    const int c = blockIdx.x * blockDim.x + threadIdx.x;
    const int chunk = blockIdx.y;
    const int b = blockIdx.z;
    const float lam = expf(-expf(nu_log[c]));
    const float gamma = expf(nu_log[c] + gamma_log[c]) - 1.f;

    size_t p = (size_t)(b * NCHUNK + chunk) * 2 * UD + c;
    float y1 = g_part[p];
    float y2 = g_part[p + UD];

    size_t base  = ((size_t)b * LSEQ + (size_t)chunk * LC) * U3;
    size_t xbase = ((size_t)b * LSEQ + (size_t)chunk * LC) * UD;
    #pragma unroll 4
    for (int i = 0; i < LC; i++) {
        size_t off = base + (size_t)i * U3;
        float rr = g_rkv[off + c];
        float kk = g_rkv[off + UD + c];
        float kv = g_rkv[off + 2 * UD + c];
        y1 = fmaf(y1, lam, kv);
        y2 = fmaf(y2, lam, kk);
        float r = 1.f / (1.f + expf(-rr));
        float x = (y1 + gamma * kv) / (y2 + gamma * kk + 1e-6f) * r;
        g_x[xbase + (size_t)i * UD + c] = x;
    }
}

// ---------------------------------------------------------------------------
// Launch
// ---------------------------------------------------------------------------
extern "C" void kernel_launch(void* const* d_in, const int* in_sizes, int n_in,
                              void* d_out, int out_size)
{
    const float* inputs    = (const float*)d_in[0];
    const float* W_rkv     = (const float*)d_in[1];
    const float* b_rkv     = (const float*)d_in[2];
    const float* W_o       = (const float*)d_in[3];
    const float* b_o       = (const float*)d_in[4];
    const float* nu_log    = (const float*)d_in[5];
    const float* gamma_log = (const float*)d_in[6];
    float* out = (float*)d_out;

    float *p_rkv = nullptr, *p_x = nullptr;
    __nv_bfloat16 *p_Ah = nullptr, *p_Xh = nullptr, *p_B1 = nullptr, *p_B2 = nullptr;
    cudaGetSymbolAddress((void**)&p_rkv, g_rkv);
    cudaGetSymbolAddress((void**)&p_x, g_x);
    cudaGetSymbolAddress((void**)&p_Ah, g_Ah);
    cudaGetSymbolAddress((void**)&p_Xh, g_Xh);
    cudaGetSymbolAddress((void**)&p_B1, g_B1);
    cudaGetSymbolAddress((void**)&p_B2, g_B2);

    static bool attr_set = false;
    if (!attr_set) {
        cudaFuncSetAttribute(gemm_mma, cudaFuncAttributeMaxDynamicSharedMemorySize, SMEM_GEMM);
        attr_set = true;
    }

    // Operand conversion (hi/lo bf16 split; B transposed to K-major [N, 2K])
    split_rows<<<(MROWS * 256 + 255) / 256, 256>>>(inputs, p_Ah, MROWS * 256);
    split_T<<<dim3(U3 / 32, HD / 32), dim3(32, 8)>>>(W_rkv, p_B1, HD, U3);
    split_T<<<dim3(HD / 32, UD / 32), dim3(32, 8)>>>(W_o, p_B2, UD, HD);

    // GEMM1: rkv = inputs @ W_rkv + b_rkv   [16384, 3072]
    gemm_mma<<<dim3(U3 / 128, MROWS / 128), 256, SMEM_GEMM>>>(p_Ah, p_B1, b_rkv, p_rkv, U3);

    // Scan
    scan_phaseA<<<dim3(UD / 256, NCHUNK, BB), 256>>>(nu_log);
    scan_phaseB<<<dim3(UD / 256, BB), 256>>>(nu_log);
    scan_phaseC<<<dim3(UD / 256, NCHUNK, BB), 256>>>(nu_log, gamma_log);

    // GEMM2: out = x @ W_o + b_o   [16384, 1024]
    split_rows<<<(MROWS * 256 + 255) / 256, 256>>>(p_x, p_Xh, MROWS * 256);
    gemm_mma<<<dim3(HD / 128, MROWS / 128), 256, SMEM_GEMM>>>(p_Xh, p_B2, b_o, out, HD);
}